// round 12
// baseline (speedup 1.0000x reference)
#include <cuda_runtime.h>

// Problem dims (fixed)
#define T_DIM 100
#define B_DIM 128
#define F_DIM 4096
#define C_DIM 10

#define ROWS_PER_BLOCK 8          // consecutive (t,b) rows per block
#define RPAIRS (ROWS_PER_BLOCK / 2)
#define THREADS_K1 128
#define F4_DIM (F_DIM / 4)        // 1024 float4 per row
#define ITERS (F4_DIM / THREADS_K1)  // 8
#define OUTS (ROWS_PER_BLOCK * C_DIM) // 80
#define BC (B_DIM * C_DIM)        // 1280

typedef unsigned long long u64;

// Packed f32x2 ops (Blackwell): one fma-pipe instruction, two fp32 lanes.
__device__ __forceinline__ u64 mul2(u64 a, u64 b) {
    u64 d; asm("mul.rn.f32x2 %0, %1, %2;" : "=l"(d) : "l"(a), "l"(b)); return d;
}
__device__ __forceinline__ u64 fma2(u64 a, u64 b, u64 c) {
    u64 d; asm("fma.rn.f32x2 %0, %1, %2, %3;" : "=l"(d) : "l"(a), "l"(b), "l"(c)); return d;
}
__device__ __forceinline__ u64 pack2(float lo, float hi) {
    u64 d; asm("mov.b64 %0, {%1, %2};" : "=l"(d) : "f"(lo), "f"(hi)); return d;
}
__device__ __forceinline__ void unpack2(u64 p, float& lo, float& hi) {
    asm("mov.b64 {%0, %1}, %2;" : "=f"(lo), "=f"(hi) : "l"(p));
}

// Scratch for current, TRANSPOSED: g_currentT[(b*C + c) * T + t]  (512 KB)
__device__ float g_currentT[BC * T_DIM];

// ============================ Kernel 1: GEMV ============================
// current[t,b,c] = 2 * sum_f spike*mask*W[c,f] + bias[c]
// R4 recipe EXACTLY (front-batched 16x __ldcs for max MLP, row-paired f32x2,
// W amortized over 8 rows + L1-resident) with a 3-CTA/SM guarantee:
// cap = 170 regs, which the ~160-170 peak live set should just fit.
__global__ __launch_bounds__(THREADS_K1, 3)
void snn_gemv_kernel(const float* __restrict__ spike,
                     const float* __restrict__ mask,
                     const float* __restrict__ W,
                     const float* __restrict__ bias)
{
    const int row0 = blockIdx.x * ROWS_PER_BLOCK;
    const int tid  = threadIdx.x;

    const float4* sp = reinterpret_cast<const float4*>(spike) + (size_t)row0 * F4_DIM;
    const float4* mk = reinterpret_cast<const float4*>(mask)  + (size_t)row0 * F4_DIM;
    const float4* W4 = reinterpret_cast<const float4*>(W);

    // acc2[rp][c]: lo lane = row 2*rp, hi lane = row 2*rp+1  (80 regs)
    u64 acc2[RPAIRS][C_DIM];
#pragma unroll
    for (int rp = 0; rp < RPAIRS; ++rp)
#pragma unroll
        for (int c = 0; c < C_DIM; ++c)
            acc2[rp][c] = 0ull;

#pragma unroll
    for (int it = 0; it < ITERS; ++it) {
        const int f4 = tid + it * THREADS_K1;

        // Front-batch ALL 16 streaming loads (MLP_p1=16; evict-first keeps W L1-resident).
        float4 s4[ROWS_PER_BLOCK], m4[ROWS_PER_BLOCK];
#pragma unroll
        for (int r = 0; r < ROWS_PER_BLOCK; ++r) {
            s4[r] = __ldcs(&sp[(size_t)r * F4_DIM + f4]);
            m4[r] = __ldcs(&mk[(size_t)r * F4_DIM + f4]);
        }

        // x pairs: x[rp][fi] = { s*m (row 2rp), s*m (row 2rp+1) }
        u64 x[RPAIRS][4];
#pragma unroll
        for (int rp = 0; rp < RPAIRS; ++rp) {
            const float4 sa = s4[2 * rp], sb = s4[2 * rp + 1];
            const float4 ma = m4[2 * rp], mb = m4[2 * rp + 1];
            x[rp][0] = mul2(pack2(sa.x, sb.x), pack2(ma.x, mb.x));
            x[rp][1] = mul2(pack2(sa.y, sb.y), pack2(ma.y, mb.y));
            x[rp][2] = mul2(pack2(sa.z, sb.z), pack2(ma.z, mb.z));
            x[rp][3] = mul2(pack2(sa.w, sb.w), pack2(ma.w, mb.w));
        }

        // 10 W float4 L1 loads per iter amortized across 8 rows.
#pragma unroll
        for (int c = 0; c < C_DIM; ++c) {
            const float4 wv = __ldg(&W4[(size_t)c * F4_DIM + f4]);
            const u64 w0 = pack2(wv.x, wv.x);
            const u64 w1 = pack2(wv.y, wv.y);
            const u64 w2 = pack2(wv.z, wv.z);
            const u64 w3 = pack2(wv.w, wv.w);
#pragma unroll
            for (int rp = 0; rp < RPAIRS; ++rp) {
                u64 a = acc2[rp][c];
                a = fma2(x[rp][0], w0, a);
                a = fma2(x[rp][1], w1, a);
                a = fma2(x[rp][2], w2, a);
                a = fma2(x[rp][3], w3, a);
                acc2[rp][c] = a;
            }
        }
    }

    // Reduce: unpack pairs to per-row scalars, warp shuffle, cross-warp smem.
    __shared__ float sred[THREADS_K1 / 32][OUTS];
    const int lane = tid & 31;
    const int warp = tid >> 5;

#pragma unroll
    for (int rp = 0; rp < RPAIRS; ++rp) {
#pragma unroll
        for (int c = 0; c < C_DIM; ++c) {
            float vlo, vhi;
            unpack2(acc2[rp][c], vlo, vhi);
#pragma unroll
            for (int o = 16; o > 0; o >>= 1) {
                vlo += __shfl_down_sync(0xffffffffu, vlo, o);
                vhi += __shfl_down_sync(0xffffffffu, vhi, o);
            }
            if (lane == 0) {
                sred[warp][(2 * rp) * C_DIM + c]     = vlo;
                sred[warp][(2 * rp + 1) * C_DIM + c] = vhi;
            }
        }
    }
    __syncthreads();

    if (tid < OUTS) {
        const float s = sred[0][tid] + sred[1][tid] + sred[2][tid] + sred[3][tid];
        const int r = tid / C_DIM;
        const int c = tid % C_DIM;
        const int row = row0 + r;
        const int t = row / B_DIM;
        const int b = row % B_DIM;
        // 2.0f = 1/keep (dropout); bias added once. Transposed store.
        g_currentT[(size_t)(b * C_DIM + c) * T_DIM + t] = 2.0f * s + bias[c];
    }
}

// ============================ Kernel 2: scan ============================
// LIF scan, double-buffered 20-t chunks (5 float4 per buffer, ~55 regs, no
// spills): chunk k+1's 5 independent loads are in flight while chunk k's
// serial chain computes. 40 blocks x 32 threads.
#define TCHUNK 5   // float4 per chunk = 20 timesteps; 5 chunks total
__global__ __launch_bounds__(32)
void snn_scan_kernel(float* __restrict__ out)
{
    const int idx = blockIdx.x * 32 + threadIdx.x;  // 0..1279
    if (idx >= BC) return;

    const float4* cur4 = reinterpret_cast<const float4*>(g_currentT + (size_t)idx * T_DIM);

    float4 bufA[TCHUNK], bufB[TCHUNK];

    // Preload chunk 0.
#pragma unroll
    for (int i = 0; i < TCHUNK; ++i) bufA[i] = __ldg(&cur4[i]);

    float v = 0.0f;
#pragma unroll
    for (int ck = 0; ck < T_DIM / (4 * TCHUNK); ++ck) {   // 5 chunks
        // Issue next chunk's loads (independent of the chain below).
        if (ck + 1 < T_DIM / (4 * TCHUNK)) {
#pragma unroll
            for (int i = 0; i < TCHUNK; ++i)
                bufB[i] = __ldg(&cur4[(ck + 1) * TCHUNK + i]);
        }

        // LIF chain over this chunk's 20 timesteps.
#pragma unroll
        for (int i = 0; i < TCHUNK; ++i) {
            const float4 c4 = bufA[i];
            const int t = (ck * TCHUNK + i) * 4;
            float s;
            v = 0.9f * v + c4.x; s = (v - 1.0f) > 0.0f ? 1.0f : 0.0f;
            out[(size_t)(t + 0) * BC + idx] = s; v -= s;
            v = 0.9f * v + c4.y; s = (v - 1.0f) > 0.0f ? 1.0f : 0.0f;
            out[(size_t)(t + 1) * BC + idx] = s; v -= s;
            v = 0.9f * v + c4.z; s = (v - 1.0f) > 0.0f ? 1.0f : 0.0f;
            out[(size_t)(t + 2) * BC + idx] = s; v -= s;
            v = 0.9f * v + c4.w; s = (v - 1.0f) > 0.0f ? 1.0f : 0.0f;
            out[(size_t)(t + 3) * BC + idx] = s; v -= s;
        }

        // Swap buffers.
#pragma unroll
        for (int i = 0; i < TCHUNK; ++i) bufA[i] = bufB[i];
    }
}

extern "C" void kernel_launch(void* const* d_in, const int* in_sizes, int n_in,
                              void* d_out, int out_size)
{
    const float* spike = (const float*)d_in[0];  // [T,B,F]
    const float* mask  = (const float*)d_in[1];  // [T,B,F]
    const float* W     = (const float*)d_in[2];  // [C,F]
    const float* bias  = (const float*)d_in[3];  // [C]
    float* out = (float*)d_out;                  // [T,B,C]

    const int grid1 = (T_DIM * B_DIM) / ROWS_PER_BLOCK;  // 1600

    snn_gemv_kernel<<<grid1, THREADS_K1>>>(spike, mask, W, bias);

    snn_scan_kernel<<<BC / 32, 32>>>(out);               // 40 blocks x 32 thr
}

// round 13
// speedup vs baseline: 1.1778x; 1.1778x over previous
#include <cuda_runtime.h>

// Problem dims (fixed)
#define T_DIM 100
#define B_DIM 128
#define F_DIM 4096
#define C_DIM 10

#define ROWS_PER_BLOCK 4          // consecutive (t,b) rows per block (same t)
#define RPAIRS (ROWS_PER_BLOCK / 2)
#define THREADS_K1 128
#define F4_DIM (F_DIM / 4)        // 1024 float4 per row
#define ITERS (F4_DIM / THREADS_K1)  // 8
#define OUTS (ROWS_PER_BLOCK * C_DIM) // 40
#define BC (B_DIM * C_DIM)        // 1280
#define GEMV_BLOCKS ((T_DIM * B_DIM) / ROWS_PER_BLOCK)  // 3200
#define SCAN_BLOCKS 10            // 10 x 128 threads = 1280 sequences
#define GRID_TOTAL (GEMV_BLOCKS + SCAN_BLOCKS)

typedef unsigned long long u64;

// Packed f32x2 ops (Blackwell): one fma-pipe instruction, two fp32 lanes.
__device__ __forceinline__ u64 mul2(u64 a, u64 b) {
    u64 d; asm("mul.rn.f32x2 %0, %1, %2;" : "=l"(d) : "l"(a), "l"(b)); return d;
}
__device__ __forceinline__ u64 fma2(u64 a, u64 b, u64 c) {
    u64 d; asm("fma.rn.f32x2 %0, %1, %2, %3;" : "=l"(d) : "l"(a), "l"(b), "l"(c)); return d;
}
__device__ __forceinline__ u64 pack2(float lo, float hi) {
    u64 d; asm("mov.b64 %0, {%1, %2};" : "=l"(d) : "f"(lo), "f"(hi)); return d;
}
__device__ __forceinline__ void unpack2(u64 p, float& lo, float& hi) {
    asm("mov.b64 {%0, %1}, %2;" : "=f"(lo), "=f"(hi) : "l"(p));
}

// Scratch for current, TRANSPOSED: g_currentT[(b*C + c) * T + t]  (512 KB)
__device__ float g_currentT[BC * T_DIM];
// Completion counters; both return to 0 every run (graph-replay deterministic).
__device__ int g_done = 0;       // GEMV blocks finished
__device__ int g_scan_done = 0;  // scan blocks finished

// ================= Fused kernel: GEMV blocks + scan blocks =================
// Blocks [0, 3200): R11's proven GEMV (76us): ROWS=4, 4 CTAs/SM, front-batched
//   __ldcs streams, row-paired f32x2, W L1-resident.
// Blocks [3200, 3210): spin until all GEMV blocks have arrived (release via
//   threadfence+atomic, acquire via threadfence after spin), then run the LIF
//   scan — overlapping the GEMV drain wave. Disjoint code path at function
//   entry so register allocation stays at the GEMV path's footprint.
__global__ __launch_bounds__(THREADS_K1, 4)
void snn_fused_kernel(const float* __restrict__ spike,
                      const float* __restrict__ mask,
                      const float* __restrict__ W,
                      const float* __restrict__ bias,
                      float* __restrict__ out)
{
    const int tid = threadIdx.x;

    if (blockIdx.x >= GEMV_BLOCKS) {
        // ---------------- Scan path (10 blocks x 128 threads) ----------------
        if (tid == 0) {
            while (atomicAdd(&g_done, 0) < GEMV_BLOCKS) __nanosleep(100);
        }
        __syncthreads();
        __threadfence();   // acquire: GEMV stores visible

        const int idx = (blockIdx.x - GEMV_BLOCKS) * THREADS_K1 + tid;  // 0..1279

        const float4* cur4 =
            reinterpret_cast<const float4*>(g_currentT + (size_t)idx * T_DIM);

        // Proven R4 scan body: batch all 25 float4 loads (MLP=25), then chain.
        float vals[T_DIM];
#pragma unroll
        for (int i = 0; i < T_DIM / 4; ++i) {
            const float4 c4 = cur4[i];
            vals[4 * i + 0] = c4.x;
            vals[4 * i + 1] = c4.y;
            vals[4 * i + 2] = c4.z;
            vals[4 * i + 3] = c4.w;
        }

        float v = 0.0f;
#pragma unroll
        for (int t = 0; t < T_DIM; ++t) {
            v = 0.9f * v + vals[t];
            const float s = (v - 1.0f) > 0.0f ? 1.0f : 0.0f;
            out[(size_t)t * BC + idx] = s;   // coalesced across threads
            v -= s;
        }

        // Counter reset: last scan block zeroes both counters.
        __syncthreads();
        if (tid == 0) {
            const int o = atomicAdd(&g_scan_done, 1);
            if (o == SCAN_BLOCKS - 1) {
                g_done = 0;
                __threadfence();
                g_scan_done = 0;
            }
        }
        return;
    }

    // ---------------- GEMV path (3200 blocks) — R11 verbatim ----------------
    const int row0 = blockIdx.x * ROWS_PER_BLOCK;

    const float4* sp = reinterpret_cast<const float4*>(spike) + (size_t)row0 * F4_DIM;
    const float4* mk = reinterpret_cast<const float4*>(mask)  + (size_t)row0 * F4_DIM;
    const float4* W4 = reinterpret_cast<const float4*>(W);

    // acc2[rp][c]: lo lane = row 2*rp, hi lane = row 2*rp+1  (40 regs)
    u64 acc2[RPAIRS][C_DIM];
#pragma unroll
    for (int rp = 0; rp < RPAIRS; ++rp)
#pragma unroll
        for (int c = 0; c < C_DIM; ++c)
            acc2[rp][c] = 0ull;

#pragma unroll
    for (int it = 0; it < ITERS; ++it) {
        const int f4 = tid + it * THREADS_K1;

        // Front-batch all 8 streaming loads (evict-first keeps W in L1).
        float4 s4[ROWS_PER_BLOCK], m4[ROWS_PER_BLOCK];
#pragma unroll
        for (int r = 0; r < ROWS_PER_BLOCK; ++r) {
            s4[r] = __ldcs(&sp[(size_t)r * F4_DIM + f4]);
            m4[r] = __ldcs(&mk[(size_t)r * F4_DIM + f4]);
        }

        // x pairs: x[rp][fi] = { s*m (row 2rp), s*m (row 2rp+1) }
        u64 x[RPAIRS][4];
#pragma unroll
        for (int rp = 0; rp < RPAIRS; ++rp) {
            const float4 sa = s4[2 * rp], sb = s4[2 * rp + 1];
            const float4 ma = m4[2 * rp], mb = m4[2 * rp + 1];
            x[rp][0] = mul2(pack2(sa.x, sb.x), pack2(ma.x, mb.x));
            x[rp][1] = mul2(pack2(sa.y, sb.y), pack2(ma.y, mb.y));
            x[rp][2] = mul2(pack2(sa.z, sb.z), pack2(ma.z, mb.z));
            x[rp][3] = mul2(pack2(sa.w, sb.w), pack2(ma.w, mb.w));
        }

        // 10 W float4 L1 loads per iter amortized across 4 rows.
#pragma unroll
        for (int c = 0; c < C_DIM; ++c) {
            const float4 wv = __ldg(&W4[(size_t)c * F4_DIM + f4]);
            const u64 w0 = pack2(wv.x, wv.x);
            const u64 w1 = pack2(wv.y, wv.y);
            const u64 w2 = pack2(wv.z, wv.z);
            const u64 w3 = pack2(wv.w, wv.w);
#pragma unroll
            for (int rp = 0; rp < RPAIRS; ++rp) {
                u64 a = acc2[rp][c];
                a = fma2(x[rp][0], w0, a);
                a = fma2(x[rp][1], w1, a);
                a = fma2(x[rp][2], w2, a);
                a = fma2(x[rp][3], w3, a);
                acc2[rp][c] = a;
            }
        }
    }

    // Reduce: unpack pairs to per-row scalars, warp shuffle, cross-warp smem.
    __shared__ float sred[THREADS_K1 / 32][OUTS];
    const int lane = tid & 31;
    const int warp = tid >> 5;

#pragma unroll
    for (int rp = 0; rp < RPAIRS; ++rp) {
#pragma unroll
        for (int c = 0; c < C_DIM; ++c) {
            float vlo, vhi;
            unpack2(acc2[rp][c], vlo, vhi);
#pragma unroll
            for (int o = 16; o > 0; o >>= 1) {
                vlo += __shfl_down_sync(0xffffffffu, vlo, o);
                vhi += __shfl_down_sync(0xffffffffu, vhi, o);
            }
            if (lane == 0) {
                sred[warp][(2 * rp) * C_DIM + c]     = vlo;
                sred[warp][(2 * rp + 1) * C_DIM + c] = vhi;
            }
        }
    }
    __syncthreads();

    if (tid < OUTS) {
        const float s = sred[0][tid] + sred[1][tid] + sred[2][tid] + sred[3][tid];
        const int r = tid / C_DIM;
        const int c = tid % C_DIM;
        const int row = row0 + r;
        const int t = row / B_DIM;
        const int b = row % B_DIM;
        // 2.0f = 1/keep (dropout); bias added once. Transposed store.
        g_currentT[(size_t)(b * C_DIM + c) * T_DIM + t] = 2.0f * s + bias[c];
    }

    // Release: stores visible, then count this block as done.
    __syncthreads();
    if (tid == 0) {
        __threadfence();
        atomicAdd(&g_done, 1);
    }
}

extern "C" void kernel_launch(void* const* d_in, const int* in_sizes, int n_in,
                              void* d_out, int out_size)
{
    const float* spike = (const float*)d_in[0];  // [T,B,F]
    const float* mask  = (const float*)d_in[1];  // [T,B,F]
    const float* W     = (const float*)d_in[2];  // [C,F]
    const float* bias  = (const float*)d_in[3];  // [C]
    float* out = (float*)d_out;                  // [T,B,C]

    snn_fused_kernel<<<GRID_TOTAL, THREADS_K1>>>(spike, mask, W, bias, out);
}

// round 14
// speedup vs baseline: 1.1986x; 1.0177x over previous
#include <cuda_runtime.h>

// Problem dims (fixed)
#define T_DIM 100
#define B_DIM 128
#define F_DIM 4096
#define C_DIM 10

#define ROWS_PER_BLOCK 2          // consecutive (t,b) rows per block
#define THREADS_K1 128
#define F4_DIM (F_DIM / 4)        // 1024 16-byte groups per row
#define ITERS (F4_DIM / THREADS_K1)  // 8
#define OUTS (ROWS_PER_BLOCK * C_DIM) // 20
#define BC (B_DIM * C_DIM)        // 1280

typedef unsigned long long u64;

// Packed f32x2 ops (Blackwell): one fma-pipe instruction, two fp32 lanes.
__device__ __forceinline__ u64 mul2(u64 a, u64 b) {
    u64 d; asm("mul.rn.f32x2 %0, %1, %2;" : "=l"(d) : "l"(a), "l"(b)); return d;
}
__device__ __forceinline__ u64 fma2(u64 a, u64 b, u64 c) {
    u64 d; asm("fma.rn.f32x2 %0, %1, %2, %3;" : "=l"(d) : "l"(a), "l"(b), "l"(c)); return d;
}
__device__ __forceinline__ float hsum2(u64 p) {
    float lo, hi; asm("mov.b64 {%0, %1}, %2;" : "=f"(lo), "=f"(hi) : "l"(p));
    return lo + hi;
}

// Scratch for current, TRANSPOSED: g_currentT[(b*C + c) * T + t]  (512 KB)
__device__ float g_currentT[BC * T_DIM];

// ============================ Kernel 1: GEMV ============================
// current[t,b,c] = 2 * sum_f spike*mask*W[c,f] + bias[c]
// f-PACKED lanes: x pairs and W pairs come directly from the 16B loads, so
// the mainloop has ZERO pack/duplicate instructions. ROWS=2 keeps the
// accumulators at 40 regs; total live ~78 regs -> 6 CTAs/SM (24 warps).
// Occupancy is the empirically-validated BW lever (2CTA:3.8, 4CTA:5.5 TB/s).
__global__ __launch_bounds__(THREADS_K1, 6)
void snn_gemv_kernel(const float* __restrict__ spike,
                     const float* __restrict__ mask,
                     const float* __restrict__ W,
                     const float* __restrict__ bias)
{
    const int row0 = blockIdx.x * ROWS_PER_BLOCK;
    const int tid  = threadIdx.x;

    // ulonglong2 = 16 bytes = 2 packed f32x2 pairs (adjacent f elements).
    const ulonglong2* sp = reinterpret_cast<const ulonglong2*>(spike) + (size_t)row0 * F4_DIM;
    const ulonglong2* mk = reinterpret_cast<const ulonglong2*>(mask)  + (size_t)row0 * F4_DIM;
    const ulonglong2* W2 = reinterpret_cast<const ulonglong2*>(W);

    // acc2[r][c]: f-packed pair accumulator for row r, class c (40 regs).
    u64 acc2[ROWS_PER_BLOCK][C_DIM];
#pragma unroll
    for (int r = 0; r < ROWS_PER_BLOCK; ++r)
#pragma unroll
        for (int c = 0; c < C_DIM; ++c)
            acc2[r][c] = 0ull;

#pragma unroll
    for (int it = 0; it < ITERS; ++it) {
        const int f4 = tid + it * THREADS_K1;

        // 4 streaming loads (evict-first keeps W L1-resident).
        const ulonglong2 sa = __ldcs(&sp[f4]);
        const ulonglong2 sb = __ldcs(&sp[(size_t)F4_DIM + f4]);
        const ulonglong2 ma = __ldcs(&mk[f4]);
        const ulonglong2 mb = __ldcs(&mk[(size_t)F4_DIM + f4]);

        // x = spike*mask, already lane-packed by the load. 4 mul2 total.
        const u64 x0lo = mul2(sa.x, ma.x);
        const u64 x0hi = mul2(sa.y, ma.y);
        const u64 x1lo = mul2(sb.x, mb.x);
        const u64 x1hi = mul2(sb.y, mb.y);

        // 10 W 16B loads per iter (L1-resident), no duplication needed.
#pragma unroll
        for (int c = 0; c < C_DIM; ++c) {
            const ulonglong2 wv = __ldg(&W2[(size_t)c * F4_DIM + f4]);
            acc2[0][c] = fma2(x0lo, wv.x, acc2[0][c]);
            acc2[0][c] = fma2(x0hi, wv.y, acc2[0][c]);
            acc2[1][c] = fma2(x1lo, wv.x, acc2[1][c]);
            acc2[1][c] = fma2(x1hi, wv.y, acc2[1][c]);
        }
    }

    // Reduce: horizontal pair-sum, warp shuffle, cross-warp smem.
    __shared__ float sred[THREADS_K1 / 32][OUTS];
    const int lane = tid & 31;
    const int warp = tid >> 5;

#pragma unroll
    for (int r = 0; r < ROWS_PER_BLOCK; ++r) {
#pragma unroll
        for (int c = 0; c < C_DIM; ++c) {
            float v = hsum2(acc2[r][c]);
#pragma unroll
            for (int o = 16; o > 0; o >>= 1)
                v += __shfl_down_sync(0xffffffffu, v, o);
            if (lane == 0)
                sred[warp][r * C_DIM + c] = v;
        }
    }
    __syncthreads();

    if (tid < OUTS) {
        const float s = sred[0][tid] + sred[1][tid] + sred[2][tid] + sred[3][tid];
        const int r = tid / C_DIM;
        const int c = tid % C_DIM;
        const int row = row0 + r;
        const int t = row / B_DIM;
        const int b = row % B_DIM;
        // 2.0f = 1/keep (dropout); bias added once. Transposed store.
        g_currentT[(size_t)(b * C_DIM + c) * T_DIM + t] = 2.0f * s + bias[c];
    }
}

// ============================ Kernel 2: scan ============================
// Proven R4 form (~7us): 40 blocks x 32 threads, batch all 25 float4 loads
// up front (MLP=25), then run the serial LIF chain.
__global__ __launch_bounds__(32)
void snn_scan_kernel(float* __restrict__ out)
{
    const int idx = blockIdx.x * 32 + threadIdx.x;  // 0..1279
    if (idx >= BC) return;

    const float4* cur4 = reinterpret_cast<const float4*>(g_currentT + (size_t)idx * T_DIM);

    float vals[T_DIM];
#pragma unroll
    for (int i = 0; i < T_DIM / 4; ++i) {
        const float4 c4 = cur4[i];
        vals[4 * i + 0] = c4.x;
        vals[4 * i + 1] = c4.y;
        vals[4 * i + 2] = c4.z;
        vals[4 * i + 3] = c4.w;
    }

    float v = 0.0f;
#pragma unroll
    for (int t = 0; t < T_DIM; ++t) {
        v = 0.9f * v + vals[t];
        const float s = (v - 1.0f) > 0.0f ? 1.0f : 0.0f;
        out[(size_t)t * BC + idx] = s;   // coalesced across threads
        v -= s;
    }
}

extern "C" void kernel_launch(void* const* d_in, const int* in_sizes, int n_in,
                              void* d_out, int out_size)
{
    const float* spike = (const float*)d_in[0];  // [T,B,F]
    const float* mask  = (const float*)d_in[1];  // [T,B,F]
    const float* W     = (const float*)d_in[2];  // [C,F]
    const float* bias  = (const float*)d_in[3];  // [C]
    float* out = (float*)d_out;                  // [T,B,C]

    const int grid1 = (T_DIM * B_DIM) / ROWS_PER_BLOCK;  // 6400

    snn_gemv_kernel<<<grid1, THREADS_K1>>>(spike, mask, W, bias);

    snn_scan_kernel<<<BC / 32, 32>>>(out);               // 40 blocks x 32 thr
}